// round 3
// baseline (speedup 1.0000x reference)
#include <cuda_runtime.h>

#define BATCH 8
#define CIN   64
#define COUT  64
#define HH    112
#define WW    112
#define HWSZ  (HH*WW)
#define LTOT  (HH*WW)

// ---------------- packed f32x2 helpers ----------------
__device__ __forceinline__ unsigned long long pk2(float a, float b) {
    unsigned long long r;
    asm("mov.b64 %0, {%1, %2};" : "=l"(r) : "f"(a), "f"(b));
    return r;
}
__device__ __forceinline__ void upk2(unsigned long long v, float& a, float& b) {
    asm("mov.b64 {%0, %1}, %2;" : "=f"(a), "=f"(b) : "l"(v));
}
__device__ __forceinline__ void ffma2(unsigned long long& d,
                                      unsigned long long a, unsigned long long b) {
    asm("fma.rn.f32x2 %0, %1, %2, %0;" : "+l"(d) : "l"(a), "l"(b));
}

// ================= K1: pure (unmasked) 3x3 conv =================
#define TH 8
#define TW 16
#define IN_H 10
#define IN_W 18
#define IN_STRIDE 20       // 16B-aligned rows for float4 LDS
#define NT1 256

__global__ __launch_bounds__(NT1, 2)
void conv_kernel(const float* __restrict__ x,
                 const float* __restrict__ w,
                 float*       __restrict__ out)
{
    __shared__ float  s_in[2][IN_H * IN_STRIDE];
    __shared__ __align__(16) float2 s_w[2][9 * COUT];   // duplicated {w,w}, layout [t][o]

    const int tid   = threadIdx.x;
    const int o_grp = tid >> 5;            // warp -> 8 output channels
    const int lane  = tid & 31;
    const int row   = lane >> 2;           // 0..7
    const int x0    = (lane & 3) << 2;     // 0,4,8,12

    const int gx0 = blockIdx.x * TW;
    const int gy0 = blockIdx.y * TH;
    const int b   = blockIdx.z;
    const int y   = gy0 + row;

    const float* xb = x + (size_t)b * CIN * HWSZ;

    // ---- loader precompute (hoisted out of channel loop) ----
    // input tile: one element per thread (tid < 180)
    bool in_act = tid < IN_H * IN_W;
    int  r_in = 0, c_in = 0;
    bool in_pred = false;
    const float* gin = xb;
    int sts_idx = 0;
    if (in_act) {
        r_in = tid / IN_W;
        c_in = tid - r_in * IN_W;
        int gy = gy0 - 1 + r_in;
        int gx = gx0 - 1 + c_in;
        in_pred = (gy >= 0 && gy < HH && gx >= 0 && gx < WW);
        gin = xb + (in_pred ? (gy * WW + gx) : 0);
        sts_idx = r_in * IN_STRIDE + c_in;
    }
    // weight entries: up to 3 per thread; smem layout [t][o]
    int widx[3];
    const float* wg[3];
    bool wact[3];
    #pragma unroll
    for (int k = 0; k < 3; k++) {
        int e = tid + k * 256;
        wact[k] = (e < 576);
        int o = 0, t = 0;
        if (wact[k]) { o = e / 9; t = e - 9 * o; }
        widx[k] = t * 64 + o;
        wg[k]   = w + o * (CIN * 9) + t;   // + c*9 per channel
    }

    // ---- prefetch channel 0 into registers ----
    float vin = (in_act && in_pred) ? __ldg(gin) : 0.0f;
    float vwr[3];
    #pragma unroll
    for (int k = 0; k < 3; k++) vwr[k] = wact[k] ? __ldg(wg[k]) : 0.0f;

    unsigned long long acc[8][2];
    #pragma unroll
    for (int o = 0; o < 8; o++) { acc[o][0] = 0ull; acc[o][1] = 0ull; }

    int buf = 0;
    for (int c = 0; c < CIN; c++) {
        // stage prefetched channel into smem
        if (in_act) s_in[buf][sts_idx] = in_pred ? vin : 0.0f;
        #pragma unroll
        for (int k = 0; k < 3; k++)
            if (wact[k]) s_w[buf][widx[k]] = make_float2(vwr[k], vwr[k]);
        __syncthreads();

        // prefetch next channel (LDG latency hides under compute)
        if (c + 1 < CIN) {
            if (in_act && in_pred) vin = __ldg(gin + (c + 1) * HWSZ);
            #pragma unroll
            for (int k = 0; k < 3; k++)
                if (wact[k]) vwr[k] = __ldg(wg[k] + (c + 1) * 9);
        }

        // register-cache the 3x8 input window
        float iv[3][8];
        const float* sb = s_in[buf];
        #pragma unroll
        for (int kh = 0; kh < 3; kh++) {
            float4 a = *reinterpret_cast<const float4*>(&sb[(row + kh) * IN_STRIDE + x0]);
            float4 bq = *reinterpret_cast<const float4*>(&sb[(row + kh) * IN_STRIDE + x0 + 4]);
            iv[kh][0] = a.x;  iv[kh][1] = a.y;  iv[kh][2] = a.z;  iv[kh][3] = a.w;
            iv[kh][4] = bq.x; iv[kh][5] = bq.y; iv[kh][6] = bq.z; iv[kh][7] = bq.w;
        }

        const float2* ws = &s_w[buf][o_grp * 8];
        #pragma unroll
        for (int kh = 0; kh < 3; kh++) {
            #pragma unroll
            for (int kw = 0; kw < 3; kw++) {
                const int t = kh * 3 + kw;
                unsigned long long v0 = pk2(iv[kh][kw + 0], iv[kh][kw + 1]);
                unsigned long long v1 = pk2(iv[kh][kw + 2], iv[kh][kw + 3]);
                #pragma unroll
                for (int o = 0; o < 8; o++) {
                    unsigned long long wv =
                        *reinterpret_cast<const unsigned long long*>(&ws[t * 64 + o]);
                    ffma2(acc[o][0], v0, wv);
                    ffma2(acc[o][1], v1, wv);
                }
            }
        }
        __syncthreads();
        buf ^= 1;
    }

    // store: 8 o x 4 contiguous x per thread (float4, 16B aligned)
    const int o_base = o_grp * 8;
    #pragma unroll
    for (int o = 0; o < 8; o++) {
        float f0, f1, f2, f3;
        upk2(acc[o][0], f0, f1);
        upk2(acc[o][1], f2, f3);
        float* dst = out + ((((size_t)b * COUT + o_base + o) * HH + y) * WW + gx0 + x0);
        *reinterpret_cast<float4*>(dst) = make_float4(f0, f1, f2, f3);
    }
}

// ================= K2: subtract masked-tap correction =================
// out[b,o,l] -= sum_c x[b,c,masked_pos(l)] * w[o,c,m[l]]
#define K2_TSTRIDE 66              // padded t-stride -> conflict-free tap-indexed LDS
#define K2_CSTRIDE (9 * K2_TSTRIDE)

__global__ __launch_bounds__(256, 2)
void corr_kernel(const float* __restrict__ x,
                 const float* __restrict__ w,
                 const int*   __restrict__ mask,
                 float*       __restrict__ out)
{
    __shared__ int   s_off[256];
    __shared__ float s_x[8 * 256];
    __shared__ __align__(16) float s_w[8 * K2_CSTRIDE];

    const int tid = threadIdx.x;
    const int b   = blockIdx.y;
    const int l   = blockIdx.x * 256 + tid;

    const int t  = mask[l];
    const int yy = l / WW;
    const int xx = l - yy * WW;
    const int kh = t / 3;
    const int kw = t - kh * 3;
    const int ym = yy + kh - 1;
    const int xm = xx + kw - 1;
    const int off = (ym >= 0 && ym < HH && xm >= 0 && xm < WW) ? (ym * WW + xm) : -1;
    s_off[tid] = off;
    __syncthreads();

    const float* xb = x + (size_t)b * CIN * HWSZ;

    unsigned long long acc[32];
    #pragma unroll
    for (int op = 0; op < 32; op++) acc[op] = 0ull;

    const int wb_t = t * K2_TSTRIDE;

    for (int cb = 0; cb < 8; cb++) {
        // gather x at the masked position for 8 channels (coalesced across lanes)
        const int myoff = off;
        #pragma unroll
        for (int k = 0; k < 8; k++) {
            float v = (myoff >= 0) ? __ldg(xb + (cb * 8 + k) * HWSZ + myoff) : 0.0f;
            s_x[k * 256 + tid] = v;
        }
        // stage weight block [8c][9t][64o] with padded t-stride
        #pragma unroll
        for (int j = 0; j < 18; j++) {
            int f  = j * 256 + tid;            // 0..4607
            int o  = f / 72;
            int r  = f - 72 * o;
            int cl = r / 9;
            int tt = r - 9 * cl;
            s_w[cl * K2_CSTRIDE + tt * K2_TSTRIDE + o] =
                __ldg(w + o * (CIN * 9) + (cb * 8 + cl) * 9 + tt);
        }
        __syncthreads();

        #pragma unroll
        for (int cl = 0; cl < 8; cl++) {
            float xv = s_x[cl * 256 + tid];
            unsigned long long xd = pk2(xv, xv);
            const float* wp = &s_w[cl * K2_CSTRIDE + wb_t];
            #pragma unroll
            for (int op = 0; op < 32; op++) {
                unsigned long long w2 =
                    *reinterpret_cast<const unsigned long long*>(wp + 2 * op);
                ffma2(acc[op], xd, w2);
            }
        }
        __syncthreads();
    }

    // subtract (coalesced across lanes: consecutive l per fixed o)
    float* ob = out + (size_t)b * COUT * LTOT + l;
    #pragma unroll
    for (int op = 0; op < 32; op++) {
        float c0, c1;
        upk2(acc[op], c0, c1);
        ob[(2 * op + 0) * (size_t)LTOT] -= c0;
        ob[(2 * op + 1) * (size_t)LTOT] -= c1;
    }
}

// ================= launch =================
extern "C" void kernel_launch(void* const* d_in, const int* in_sizes, int n_in,
                              void* d_out, int out_size)
{
    (void)in_sizes; (void)n_in; (void)out_size;
    const float* x    = (const float*)d_in[0];
    const float* w    = (const float*)d_in[1];
    const int*   mask = (const int*)d_in[2];
    float*       out  = (float*)d_out;

    dim3 g1(WW / TW, HH / TH, BATCH);     // 7 x 14 x 8 = 784 CTAs
    conv_kernel<<<g1, NT1>>>(x, w, out);

    dim3 g2(LTOT / 256, BATCH);           // 49 x 8 = 392 CTAs
    corr_kernel<<<g2, 256>>>(x, w, mask, out);
}

// round 6
// speedup vs baseline: 4.0964x; 4.0964x over previous
#include <cuda_runtime.h>
#include <cuda_bf16.h>
#include <cstdint>

#define BATCH 8
#define CIN   64
#define COUT  64
#define HH    112
#define WW    112
#define HWSZ  (HH*WW)

// ---------------- precomputed bf16-split planes ----------------
// x_t: [b][y][x][c] (c contiguous: 64*2B = 128B rows)
__device__ __align__(128) __nv_bfloat16 g_x_hi[BATCH * HH * WW * CIN];
__device__ __align__(128) __nv_bfloat16 g_x_lo[BATCH * HH * WW * CIN];
// w_t: [t][o][c]
__device__ __align__(128) __nv_bfloat16 g_w_hi[9 * COUT * CIN];
__device__ __align__(128) __nv_bfloat16 g_w_lo[9 * COUT * CIN];

// ================= prep: transpose + hi/lo split =================
__global__ void xprep_kernel(const float* __restrict__ x)
{
    __shared__ float tile[CIN * WW];
    const int y = blockIdx.x, b = blockIdx.y, tid = threadIdx.x;
    for (int i = tid; i < CIN * WW; i += 256) {
        int c = i / WW, xx = i - c * WW;
        tile[c * WW + xx] = x[((b * CIN + c) * HH + y) * WW + xx];
    }
    __syncthreads();
    for (int i = tid; i < CIN * WW; i += 256) {
        int xx = i >> 6, c = i & 63;
        float v = tile[c * WW + xx];
        __nv_bfloat16 hi = __float2bfloat16(v);
        float lo = v - __bfloat162float(hi);
        size_t idx = ((size_t)(b * HH + y) * WW + xx) * CIN + c;
        g_x_hi[idx] = hi;
        g_x_lo[idx] = __float2bfloat16(lo);
    }
}

__global__ void wprep_kernel(const float* __restrict__ w)
{
    int i = blockIdx.x * 256 + threadIdx.x;
    if (i >= 9 * COUT * CIN) return;
    int c = i & 63, o = (i >> 6) & 63, t = i >> 12;
    float v = w[o * (CIN * 9) + c * 9 + t];
    __nv_bfloat16 hi = __float2bfloat16(v);
    float lo = v - __bfloat162float(hi);
    int idx = (t * COUT + o) * CIN + c;
    g_w_hi[idx] = hi;
    g_w_lo[idx] = __float2bfloat16(lo);
}

// ================= base-ISA async/MMA primitives =================
__device__ __forceinline__ uint32_t smem_u32(const void* p) {
    uint32_t a;
    asm("{ .reg .u64 t; cvta.to.shared.u64 t, %1; cvt.u32.u64 %0, t; }" : "=r"(a) : "l"(p));
    return a;
}
__device__ __forceinline__ void cp16(uint32_t dst, const void* src, uint32_t sz) {
    asm volatile("cp.async.cg.shared.global [%0], [%1], 16, %2;"
                 :: "r"(dst), "l"(src), "r"(sz) : "memory");
}
#define CP_COMMIT() asm volatile("cp.async.commit_group;" ::: "memory")
#define CP_WAIT0()  asm volatile("cp.async.wait_group 0;" ::: "memory")

__device__ __forceinline__ void ldmx4(uint32_t* r, uint32_t addr) {
    asm volatile("ldmatrix.sync.aligned.m8n8.x4.shared.b16 {%0,%1,%2,%3}, [%4];"
                 : "=r"(r[0]), "=r"(r[1]), "=r"(r[2]), "=r"(r[3]) : "r"(addr));
}
__device__ __forceinline__ void mma16816(float* c, const uint32_t* a,
                                         uint32_t b0, uint32_t b1) {
    asm volatile("mma.sync.aligned.m16n8k16.row.col.f32.bf16.bf16.f32 "
                 "{%0,%1,%2,%3}, {%4,%5,%6,%7}, {%8,%9}, {%0,%1,%2,%3};"
                 : "+f"(c[0]), "+f"(c[1]), "+f"(c[2]), "+f"(c[3])
                 : "r"(a[0]), "r"(a[1]), "r"(a[2]), "r"(a[3]), "r"(b0), "r"(b1));
}

// ================= main kernel =================
// smem: [0, 46080)  x tile: 2 planes x 180 rows x 128B (XOR-swizzled)
//       [46080, 46208) zero row (128B)
//       [46208, 78976) B double buffer: 2 bufs x {hi 8K | lo 8K}
// epilogue reuses [0, 33792) as C[128][66] fp32.
#define X_OFF   0
#define XPL     23040
#define Z_OFF   46080
#define B_OFF   46208
#define B_BUF   16384
#define B_PL    8192
#define SMEM_SZ 78976

__global__ __launch_bounds__(256, 2)
void rconv_mma_kernel(const int* __restrict__ mask, float* __restrict__ out)
{
    extern __shared__ __align__(128) char smem[];
    const uint32_t sb = smem_u32(smem);

    const int tid  = threadIdx.x;
    const int wid  = tid >> 5;
    const int lane = tid & 31;
    const int tile = blockIdx.x;            // 0..97
    const int b    = blockIdx.y;
    const int x0   = (tile % 7) * 16;
    const int y0   = (tile / 7) * 8;

    const int wm = wid & 3;                 // m-tile: 32 rows
    const int wn = wid >> 2;                // n-tile: 32 cols
    const int m0 = wm * 32;
    const int n0 = wn * 32;

    // zero row
    if (tid < 32) ((float*)(smem + Z_OFF))[tid] = 0.0f;

    // ---- per-thread ldmatrix geometry ----
    // A: lanes 0-15 -> rows 0-15 (k-half 0), 16-31 -> same rows (k-half 1)
    const int ch       = lane >> 4;         // A k-half
    const int lanerow  = lane & 15;
    int  rb[2], mk[2];                      // per m16-tile: staged-row base, mask tap
    #pragma unroll
    for (int mi = 0; mi < 2; mi++) {
        int p  = m0 + mi * 16 + lanerow;    // position 0..127
        int py = p >> 4, px = p & 15;
        rb[mi] = py * 18 + px;
        mk[mi] = mask[(y0 + py) * WW + (x0 + px)];
    }
    // B: nlocal = (lane&7) + 8*(lane>=16); khalf = (lane>>3)&1
    const int nlocal = (lane & 7) + ((lane >> 4) << 3);
    const int khalf  = (lane >> 3) & 1;
    int boff[2], bsw[2];
    #pragma unroll
    for (int ntp = 0; ntp < 2; ntp++) {
        int orow = n0 + ntp * 16 + nlocal;
        boff[ntp] = orow * 128;
        bsw[ntp]  = orow & 7;
    }
    const uint32_t zaddr = sb + Z_OFF;

    // ---- prologue: stage x tile (both planes) + B[0] ----
    for (int i = tid; i < 2880; i += 256) {
        int plane = i / 1440;
        int rem   = i - plane * 1440;
        int r     = rem >> 3;
        int j     = rem & 7;
        int iy    = r / 18, ix = r - iy * 18;
        int gy    = y0 - 1 + iy, gx = x0 - 1 + ix;
        bool ok   = (gy >= 0 && gy < HH && gx >= 0 && gx < WW);
        const __nv_bfloat16* base = plane ? g_x_lo : g_x_hi;
        const __nv_bfloat16* src  = base +
            (ok ? (((size_t)((b * HH + gy) * WW + gx)) * CIN + j * 8) : 0);
        uint32_t dst = sb + X_OFF + plane * XPL + r * 128 + ((j ^ (r & 7)) << 4);
        cp16(dst, src, ok ? 16u : 0u);
    }
    {   // B[0] -> buf 0
        for (int i = tid; i < 1024; i += 256) {
            int plane = i >> 9, rem = i & 511;
            int o = rem >> 3, j = rem & 7;
            const __nv_bfloat16* src = (plane ? g_w_lo : g_w_hi) + ((0 * 64 + o) * 64 + j * 8);
            uint32_t dst = sb + B_OFF + 0 * B_BUF + plane * B_PL + o * 128 + ((j ^ (o & 7)) << 4);
            cp16(dst, src, 16u);
        }
    }
    CP_COMMIT();

    float C[2][4][4];
    #pragma unroll
    for (int mi = 0; mi < 2; mi++)
        #pragma unroll
        for (int nt = 0; nt < 4; nt++)
            #pragma unroll
            for (int k = 0; k < 4; k++) C[mi][nt][k] = 0.0f;

    int buf = 0;
    #pragma unroll 1
    for (int t = 0; t < 9; t++) {
        CP_WAIT0();
        __syncthreads();

        if (t < 8) {  // prefetch B[t+1] into other buffer (overlaps compute)
            for (int i = tid; i < 1024; i += 256) {
                int plane = i >> 9, rem = i & 511;
                int o = rem >> 3, j = rem & 7;
                const __nv_bfloat16* src = (plane ? g_w_lo : g_w_hi) + (((t + 1) * 64 + o) * 64 + j * 8);
                uint32_t dst = sb + B_OFF + (buf ^ 1) * B_BUF + plane * B_PL
                             + o * 128 + ((j ^ (o & 7)) << 4);
                cp16(dst, src, 16u);
            }
            CP_COMMIT();
        }

        const int kh   = t / 3;
        const int toff = t + kh * 15;        // kh*18 + kw
        int  r128[2], rm[2];
        bool msk[2];
        #pragma unroll
        for (int mi = 0; mi < 2; mi++) {
            int r = rb[mi] + toff;
            r128[mi] = r << 7;
            rm[mi]   = r & 7;
            msk[mi]  = (mk[mi] == t);
        }
        const uint32_t bb = sb + B_OFF + buf * B_BUF;

        #pragma unroll
        for (int kc = 0; kc < 4; kc++) {
            uint32_t AH[2][4], AL[2][4], BH[2][4], BL[2][4];
            #pragma unroll
            for (int mi = 0; mi < 2; mi++) {
                uint32_t sw = (uint32_t)((((kc << 1) | ch) ^ rm[mi]) << 4);
                uint32_t ah = msk[mi] ? zaddr : (sb + X_OFF + r128[mi] + sw);
                uint32_t al = msk[mi] ? zaddr : (ah + XPL);
                ldmx4(AH[mi], ah);
                ldmx4(AL[mi], al);
            }
            #pragma unroll
            for (int ntp = 0; ntp < 2; ntp++) {
                uint32_t sw = (uint32_t)((((kc << 1) | khalf) ^ bsw[ntp]) << 4);
                uint32_t bh = bb + boff[ntp] + sw;
                ldmx4(BH[ntp], bh);
                ldmx4(BL[ntp], bh + B_PL);
            }
            #pragma unroll
            for (int mi = 0; mi < 2; mi++)
                #pragma unroll
                for (int ntp = 0; ntp < 2; ntp++)
                    #pragma unroll
                    for (int s = 0; s < 2; s++) {
                        float* acc = C[mi][ntp * 2 + s];
                        mma16816(acc, AH[mi], BH[ntp][2 * s], BH[ntp][2 * s + 1]);
                        mma16816(acc, AL[mi], BH[ntp][2 * s], BH[ntp][2 * s + 1]);
                        mma16816(acc, AH[mi], BL[ntp][2 * s], BL[ntp][2 * s + 1]);
                    }
        }
        buf ^= 1;
    }

    // ---- epilogue: C -> smem [m][o] (stride 66), then coalesced float4 stores ----
    __syncthreads();
    float* sC = (float*)smem;
    const int g   = lane >> 2;
    const int tg2 = (lane & 3) * 2;
    #pragma unroll
    for (int mi = 0; mi < 2; mi++)
        #pragma unroll
        for (int nt = 0; nt < 4; nt++) {
            int mrow = m0 + mi * 16 + g;
            int col  = n0 + nt * 8 + tg2;
            *(float2*)(sC + mrow * 66 + col)       = make_float2(C[mi][nt][0], C[mi][nt][1]);
            *(float2*)(sC + (mrow + 8) * 66 + col) = make_float2(C[mi][nt][2], C[mi][nt][3]);
        }
    __syncthreads();

    #pragma unroll
    for (int it = 0; it < 8; it++) {
        int idx = it * 256 + tid;          // (o, py, q)
        int o   = idx >> 5;
        int rem = idx & 31;
        int py  = rem >> 2;
        int px  = (rem & 3) * 4;
        int mb  = py * 16 + px;
        float4 v;
        v.x = sC[(mb + 0) * 66 + o];
        v.y = sC[(mb + 1) * 66 + o];
        v.z = sC[(mb + 2) * 66 + o];
        v.w = sC[(mb + 3) * 66 + o];
        *(float4*)(out + ((size_t)(b * COUT + o)) * HWSZ + (y0 + py) * WW + (x0 + px)) = v;
    }
}

// ================= launch =================
extern "C" void kernel_launch(void* const* d_in, const int* in_sizes, int n_in,
                              void* d_out, int out_size)
{
    (void)in_sizes; (void)n_in; (void)out_size;
    const float* x    = (const float*)d_in[0];
    const float* w    = (const float*)d_in[1];
    const int*   mask = (const int*)d_in[2];
    float*       out  = (float*)d_out;

    xprep_kernel<<<dim3(HH, BATCH), 256>>>(x);
    wprep_kernel<<<(9 * COUT * CIN + 255) / 256, 256>>>(w);

    cudaFuncSetAttribute(rconv_mma_kernel,
                         cudaFuncAttributeMaxDynamicSharedMemorySize, SMEM_SZ);
    rconv_mma_kernel<<<dim3(98, BATCH), 256, SMEM_SZ>>>(mask, out);
}

// round 7
// speedup vs baseline: 8.1243x; 1.9833x over previous
#include <cuda_runtime.h>
#include <cuda_fp16.h>
#include <cstdint>

#define BATCH 8
#define CIN   64
#define COUT  64
#define HH    112
#define WW    112
#define HWSZ  (HH*WW)

// ---------------- precomputed fp16 planes ----------------
// x_h: [b][y][x][c] (c contiguous: 64*2B = 128B rows)
__device__ __align__(128) __half g_x_h[BATCH * HH * WW * CIN];
// w_h: [t][o][c]
__device__ __align__(128) __half g_w_h[9 * COUT * CIN];

// ================= prep: transpose + fp16 convert =================
__global__ void xprep_kernel(const float* __restrict__ x)
{
    __shared__ float tile[CIN * 113];          // padded stride: no 16-way conflicts
    const int y = blockIdx.x, b = blockIdx.y, tid = threadIdx.x;

    for (int i = tid; i < CIN * 28; i += 256) {        // coalesced float4 reads
        int c = i / 28, q = i - c * 28;
        float4 v = *(const float4*)&x[(((size_t)b * CIN + c) * HH + y) * WW + q * 4];
        float* d = &tile[c * 113 + q * 4];
        d[0] = v.x; d[1] = v.y; d[2] = v.z; d[3] = v.w;
    }
    __syncthreads();

    for (int i = tid; i < 896; i += 256) {             // uint4 coalesced writes
        int xx = i >> 3, cg = i & 7;
        __half h[8];
        #pragma unroll
        for (int k = 0; k < 8; k++)
            h[k] = __float2half(tile[(cg * 8 + k) * 113 + xx]);
        *(uint4*)&g_x_h[((size_t)((b * HH + y) * WW) + xx) * 64 + cg * 8] = *(uint4*)h;
    }
}

__global__ void wprep_kernel(const float* __restrict__ w)
{
    int i = blockIdx.x * 256 + threadIdx.x;
    if (i >= 9 * COUT * CIN) return;
    int c = i & 63, o = (i >> 6) & 63, t = i >> 12;
    g_w_h[(t * COUT + o) * CIN + c] = __float2half(w[o * (CIN * 9) + c * 9 + t]);
}

// ================= base-ISA async/MMA primitives =================
__device__ __forceinline__ uint32_t smem_u32(const void* p) {
    uint32_t a;
    asm("{ .reg .u64 t; cvta.to.shared.u64 t, %1; cvt.u32.u64 %0, t; }" : "=r"(a) : "l"(p));
    return a;
}
__device__ __forceinline__ void cp16(uint32_t dst, const void* src, uint32_t sz) {
    asm volatile("cp.async.cg.shared.global [%0], [%1], 16, %2;"
                 :: "r"(dst), "l"(src), "r"(sz) : "memory");
}
#define CP_COMMIT() asm volatile("cp.async.commit_group;" ::: "memory")
#define CP_WAIT0()  asm volatile("cp.async.wait_group 0;" ::: "memory")

__device__ __forceinline__ void ldmx4(uint32_t* r, uint32_t addr) {
    asm volatile("ldmatrix.sync.aligned.m8n8.x4.shared.b16 {%0,%1,%2,%3}, [%4];"
                 : "=r"(r[0]), "=r"(r[1]), "=r"(r[2]), "=r"(r[3]) : "r"(addr));
}
__device__ __forceinline__ void mma16816(float* c, const uint32_t* a,
                                         uint32_t b0, uint32_t b1) {
    asm volatile("mma.sync.aligned.m16n8k16.row.col.f32.f16.f16.f32 "
                 "{%0,%1,%2,%3}, {%4,%5,%6,%7}, {%8,%9}, {%0,%1,%2,%3};"
                 : "+f"(c[0]), "+f"(c[1]), "+f"(c[2]), "+f"(c[3])
                 : "r"(a[0]), "r"(a[1]), "r"(a[2]), "r"(a[3]), "r"(b0), "r"(b1));
}

// ================= main kernel =================
// smem: [0, 23040)  x tile: 180 rows x 128B (XOR-swizzled)
//       [23040, 23168) zero row
//       [23168, 39552) B double buffer: 2 x 8KB
// epilogue reuses [0, 33792) as C[128][66] fp32.
#define X_OFF   0
#define Z_OFF   23040
#define B_OFF   23168
#define B_BUF   8192
#define SMEM_SZ 39552

__global__ __launch_bounds__(256, 3)
void rconv_mma_kernel(const int* __restrict__ mask, float* __restrict__ out)
{
    extern __shared__ __align__(128) char smem[];
    const uint32_t sb = smem_u32(smem);

    const int tid  = threadIdx.x;
    const int wid  = tid >> 5;
    const int lane = tid & 31;
    const int tile = blockIdx.x;            // 0..97
    const int b    = blockIdx.y;
    const int x0   = (tile % 7) * 16;
    const int y0   = (tile / 7) * 8;

    const int wm = wid & 3;                 // m-tile: 32 rows
    const int wn = wid >> 2;                // n-tile: 32 cols
    const int m0 = wm * 32;
    const int n0 = wn * 32;

    if (tid < 32) ((float*)(smem + Z_OFF))[tid] = 0.0f;

    // ---- per-thread ldmatrix geometry ----
    const int ch      = lane >> 4;          // A k-half
    const int lanerow = lane & 15;
    int  rb[2], mk[2];
    #pragma unroll
    for (int mi = 0; mi < 2; mi++) {
        int p  = m0 + mi * 16 + lanerow;    // position 0..127
        int py = p >> 4, px = p & 15;
        rb[mi] = py * 18 + px;
        mk[mi] = mask[(y0 + py) * WW + (x0 + px)];
    }
    const int nlocal = (lane & 7) + ((lane >> 4) << 3);
    const int khalf  = (lane >> 3) & 1;
    int boff[2], bsw[2];
    #pragma unroll
    for (int ntp = 0; ntp < 2; ntp++) {
        int orow = n0 + ntp * 16 + nlocal;
        boff[ntp] = orow * 128;
        bsw[ntp]  = orow & 7;
    }
    const uint32_t zaddr = sb + Z_OFF;

    // ---- prologue: stage x tile + B[0] ----
    for (int i = tid; i < 1440; i += 256) {
        int r  = i >> 3;
        int j  = i & 7;
        int iy = r / 18, ix = r - iy * 18;
        int gy = y0 - 1 + iy, gx = x0 - 1 + ix;
        bool ok = (gy >= 0 && gy < HH && gx >= 0 && gx < WW);
        const __half* src = g_x_h +
            (ok ? (((size_t)((b * HH + gy) * WW + gx)) * CIN + j * 8) : 0);
        uint32_t dst = sb + X_OFF + r * 128 + ((j ^ (r & 7)) << 4);
        cp16(dst, src, ok ? 16u : 0u);
    }
    for (int i = tid; i < 512; i += 256) {
        int o = i >> 3, j = i & 7;
        const __half* src = g_w_h + ((0 * COUT + o) * CIN + j * 8);
        uint32_t dst = sb + B_OFF + o * 128 + ((j ^ (o & 7)) << 4);
        cp16(dst, src, 16u);
    }
    CP_COMMIT();

    float C[2][4][4];
    #pragma unroll
    for (int mi = 0; mi < 2; mi++)
        #pragma unroll
        for (int nt = 0; nt < 4; nt++)
            #pragma unroll
            for (int k = 0; k < 4; k++) C[mi][nt][k] = 0.0f;

    int buf = 0;
    #pragma unroll 1
    for (int t = 0; t < 9; t++) {
        CP_WAIT0();
        __syncthreads();

        if (t < 8) {  // prefetch B[t+1] (overlaps compute)
            for (int i = tid; i < 512; i += 256) {
                int o = i >> 3, j = i & 7;
                const __half* src = g_w_h + (((t + 1) * COUT + o) * CIN + j * 8);
                uint32_t dst = sb + B_OFF + (buf ^ 1) * B_BUF + o * 128 + ((j ^ (o & 7)) << 4);
                cp16(dst, src, 16u);
            }
            CP_COMMIT();
        }

        const int kh   = t / 3;
        const int toff = t + kh * 15;        // kh*18 + kw
        int  r128[2], rm[2];
        bool msk[2];
        #pragma unroll
        for (int mi = 0; mi < 2; mi++) {
            int r = rb[mi] + toff;
            r128[mi] = r << 7;
            rm[mi]   = r & 7;
            msk[mi]  = (mk[mi] == t);
        }
        const uint32_t bb = sb + B_OFF + buf * B_BUF;

        #pragma unroll
        for (int kc = 0; kc < 4; kc++) {
            uint32_t A[2][4], Bv[2][4];
            #pragma unroll
            for (int mi = 0; mi < 2; mi++) {
                uint32_t sw = (uint32_t)((((kc << 1) | ch) ^ rm[mi]) << 4);
                uint32_t ah = msk[mi] ? zaddr : (sb + X_OFF + r128[mi] + sw);
                ldmx4(A[mi], ah);
            }
            #pragma unroll
            for (int ntp = 0; ntp < 2; ntp++) {
                uint32_t sw = (uint32_t)((((kc << 1) | khalf) ^ bsw[ntp]) << 4);
                ldmx4(Bv[ntp], bb + boff[ntp] + sw);
            }
            #pragma unroll
            for (int mi = 0; mi < 2; mi++)
                #pragma unroll
                for (int ntp = 0; ntp < 2; ntp++)
                    #pragma unroll
                    for (int s = 0; s < 2; s++)
                        mma16816(C[mi][ntp * 2 + s], A[mi],
                                 Bv[ntp][2 * s], Bv[ntp][2 * s + 1]);
        }
        buf ^= 1;
    }

    // ---- epilogue: C -> smem [m][o] (stride 66), then coalesced float4 stores ----
    __syncthreads();
    float* sC = (float*)smem;
    const int g   = lane >> 2;
    const int tg2 = (lane & 3) * 2;
    #pragma unroll
    for (int mi = 0; mi < 2; mi++)
        #pragma unroll
        for (int nt = 0; nt < 4; nt++) {
            int mrow = m0 + mi * 16 + g;
            int col  = n0 + nt * 8 + tg2;
            *(float2*)(sC + mrow * 66 + col)       = make_float2(C[mi][nt][0], C[mi][nt][1]);
            *(float2*)(sC + (mrow + 8) * 66 + col) = make_float2(C[mi][nt][2], C[mi][nt][3]);
        }
    __syncthreads();

    #pragma unroll
    for (int it = 0; it < 8; it++) {
        int idx = it * 256 + tid;          // (o, py, q)
        int o   = idx >> 5;
        int rem = idx & 31;
        int py  = rem >> 2;
        int px  = (rem & 3) * 4;
        int mb  = py * 16 + px;
        float4 v;
        v.x = sC[(mb + 0) * 66 + o];
        v.y = sC[(mb + 1) * 66 + o];
        v.z = sC[(mb + 2) * 66 + o];
        v.w = sC[(mb + 3) * 66 + o];
        *(float4*)(out + ((size_t)(b * COUT + o)) * HWSZ + (y0 + py) * WW + (x0 + px)) = v;
    }
}

// ================= launch =================
extern "C" void kernel_launch(void* const* d_in, const int* in_sizes, int n_in,
                              void* d_out, int out_size)
{
    (void)in_sizes; (void)n_in; (void)out_size;
    const float* x    = (const float*)d_in[0];
    const float* w    = (const float*)d_in[1];
    const int*   mask = (const int*)d_in[2];
    float*       out  = (float*)d_out;

    xprep_kernel<<<dim3(HH, BATCH), 256>>>(x);
    wprep_kernel<<<(9 * COUT * CIN + 255) / 256, 256>>>(w);

    cudaFuncSetAttribute(rconv_mma_kernel,
                         cudaFuncAttributeMaxDynamicSharedMemorySize, SMEM_SZ);
    rconv_mma_kernel<<<dim3(98, BATCH), 256, SMEM_SZ>>>(mask, out);
}

// round 8
// speedup vs baseline: 8.5351x; 1.0506x over previous
#include <cuda_runtime.h>
#include <cuda_fp16.h>
#include <cstdint>

#define BATCH 8
#define CIN   64
#define COUT  64
#define HH    112
#define WW    112
#define HWSZ  (HH*WW)

// ---------------- precomputed fp16 planes ----------------
// x_h: [b][y][x][c] (c contiguous: 64*2B = 128B rows)
__device__ __align__(128) __half g_x_h[BATCH * HH * WW * CIN];
// w_h: [t][o][c]
__device__ __align__(128) __half g_w_h[9 * COUT * CIN];

// ================= prep: transpose + fp16 convert =================
__global__ void xprep_kernel(const float* __restrict__ x)
{
    __shared__ float tile[CIN * 113];          // padded stride: no 16-way conflicts
    const int y = blockIdx.x, b = blockIdx.y, tid = threadIdx.x;

    for (int i = tid; i < CIN * 28; i += 256) {        // coalesced float4 reads
        int c = i / 28, q = i - c * 28;
        float4 v = *(const float4*)&x[(((size_t)b * CIN + c) * HH + y) * WW + q * 4];
        float* d = &tile[c * 113 + q * 4];
        d[0] = v.x; d[1] = v.y; d[2] = v.z; d[3] = v.w;
    }
    __syncthreads();

    for (int i = tid; i < 896; i += 256) {             // uint4 coalesced writes
        int xx = i >> 3, cg = i & 7;
        __half h[8];
        #pragma unroll
        for (int k = 0; k < 8; k++)
            h[k] = __float2half(tile[(cg * 8 + k) * 113 + xx]);
        *(uint4*)&g_x_h[((size_t)((b * HH + y) * WW) + xx) * 64 + cg * 8] = *(uint4*)h;
    }
}

__global__ void wprep_kernel(const float* __restrict__ w)
{
    int i = blockIdx.x * 256 + threadIdx.x;
    if (i >= 9 * COUT * CIN) return;
    int c = i & 63, o = (i >> 6) & 63, t = i >> 12;
    g_w_h[(t * COUT + o) * CIN + c] = __float2half(w[o * (CIN * 9) + c * 9 + t]);
}

// ================= base-ISA async/MMA primitives =================
__device__ __forceinline__ uint32_t smem_u32(const void* p) {
    uint32_t a;
    asm("{ .reg .u64 t; cvta.to.shared.u64 t, %1; cvt.u32.u64 %0, t; }" : "=r"(a) : "l"(p));
    return a;
}
__device__ __forceinline__ void cp16(uint32_t dst, const void* src, uint32_t sz) {
    asm volatile("cp.async.cg.shared.global [%0], [%1], 16, %2;"
                 :: "r"(dst), "l"(src), "r"(sz) : "memory");
}
#define CP_COMMIT() asm volatile("cp.async.commit_group;" ::: "memory")
#define CP_WAIT0()  asm volatile("cp.async.wait_group 0;" ::: "memory")

__device__ __forceinline__ void ldmx4(uint32_t* r, uint32_t addr) {
    asm volatile("ldmatrix.sync.aligned.m8n8.x4.shared.b16 {%0,%1,%2,%3}, [%4];"
                 : "=r"(r[0]), "=r"(r[1]), "=r"(r[2]), "=r"(r[3]) : "r"(addr));
}
__device__ __forceinline__ void mma16816(float* c, const uint32_t* a,
                                         uint32_t b0, uint32_t b1) {
    asm volatile("mma.sync.aligned.m16n8k16.row.col.f32.f16.f16.f32 "
                 "{%0,%1,%2,%3}, {%4,%5,%6,%7}, {%8,%9}, {%0,%1,%2,%3};"
                 : "+f"(c[0]), "+f"(c[1]), "+f"(c[2]), "+f"(c[3])
                 : "r"(a[0]), "r"(a[1]), "r"(a[2]), "r"(a[3]), "r"(b0), "r"(b1));
}

// ================= main kernel =================
// smem: [0, 23040)   x tile: 180 rows x 128B (XOR-swizzled)
//       [23040, 23168) zero row
//       [23168, 96896) B: ALL 9 taps x 8KB  (barrier-free mainloop)
// epilogue reuses [0, 33792) as C[128][66] fp32.
#define X_OFF   0
#define Z_OFF   23040
#define B_OFF   23168
#define B_TAP   8192
#define SMEM_SZ 96896

__global__ __launch_bounds__(256, 2)
void rconv_mma_kernel(const int* __restrict__ mask, float* __restrict__ out)
{
    extern __shared__ __align__(128) char smem[];
    const uint32_t sb = smem_u32(smem);

    const int tid  = threadIdx.x;
    const int wid  = tid >> 5;
    const int lane = tid & 31;
    const int tile = blockIdx.x;            // 0..97
    const int b    = blockIdx.y;
    const int x0   = (tile % 7) * 16;
    const int y0   = (tile / 7) * 8;

    const int wm = wid & 3;                 // m-tile: 32 rows
    const int wn = wid >> 2;                // n-tile: 32 cols
    const int m0 = wm * 32;
    const int n0 = wn * 32;

    if (tid < 32) ((float*)(smem + Z_OFF))[tid] = 0.0f;

    // ---- per-thread ldmatrix geometry ----
    const int ch      = lane >> 4;          // A k-half
    const int lanerow = lane & 15;
    int  rb[2], mk[2];
    #pragma unroll
    for (int mi = 0; mi < 2; mi++) {
        int p  = m0 + mi * 16 + lanerow;    // position 0..127
        int py = p >> 4, px = p & 15;
        rb[mi] = py * 18 + px;
        mk[mi] = __ldg(&mask[(y0 + py) * WW + (x0 + px)]);
    }
    const int nlocal = (lane & 7) + ((lane >> 4) << 3);
    const int khalf  = (lane >> 3) & 1;
    int boff[2], bsw[2];
    #pragma unroll
    for (int ntp = 0; ntp < 2; ntp++) {
        int orow = n0 + ntp * 16 + nlocal;
        boff[ntp] = orow * 128;
        bsw[ntp]  = orow & 7;
    }
    const uint32_t zaddr = sb + Z_OFF;

    // ---- prologue: stage x tile + ALL 9 B taps, single barrier ----
    for (int i = tid; i < 1440; i += 256) {
        int r  = i >> 3;
        int j  = i & 7;
        int iy = r / 18, ix = r - iy * 18;
        int gy = y0 - 1 + iy, gx = x0 - 1 + ix;
        bool ok = (gy >= 0 && gy < HH && gx >= 0 && gx < WW);
        const __half* src = g_x_h +
            (ok ? (((size_t)((b * HH + gy) * WW + gx)) * CIN + j * 8) : 0);
        uint32_t dst = sb + X_OFF + r * 128 + ((j ^ (r & 7)) << 4);
        cp16(dst, src, ok ? 16u : 0u);
    }
    #pragma unroll
    for (int k = 0; k < 18; k++) {          // 9 taps x 64 o x 8 j = 4608 units
        int i = k * 256 + tid;
        int t = i / 512;
        int rem = i & 511;
        int o = rem >> 3, j = rem & 7;
        const __half* src = g_w_h + ((t * COUT + o) * CIN + j * 8);
        uint32_t dst = sb + B_OFF + t * B_TAP + o * 128 + ((j ^ (o & 7)) << 4);
        cp16(dst, src, 16u);
    }
    CP_COMMIT();

    float C[2][4][4];
    #pragma unroll
    for (int mi = 0; mi < 2; mi++)
        #pragma unroll
        for (int nt = 0; nt < 4; nt++)
            #pragma unroll
            for (int k = 0; k < 4; k++) C[mi][nt][k] = 0.0f;

    CP_WAIT0();
    __syncthreads();

    // ---- barrier-free tap loop (fully unrolled) ----
    #pragma unroll
    for (int t = 0; t < 9; t++) {
        const int kh   = t / 3;
        const int toff = t + kh * 15;        // kh*18 + kw
        int  r128[2], rm[2];
        bool msk[2];
        #pragma unroll
        for (int mi = 0; mi < 2; mi++) {
            int r = rb[mi] + toff;
            r128[mi] = r << 7;
            rm[mi]   = r & 7;
            msk[mi]  = (mk[mi] == t);
        }
        const uint32_t bb = sb + B_OFF + t * B_TAP;

        #pragma unroll
        for (int kc = 0; kc < 4; kc++) {
            uint32_t A[2][4], Bv[2][4];
            #pragma unroll
            for (int mi = 0; mi < 2; mi++) {
                uint32_t sw = (uint32_t)((((kc << 1) | ch) ^ rm[mi]) << 4);
                uint32_t ah = msk[mi] ? zaddr : (sb + X_OFF + r128[mi] + sw);
                ldmx4(A[mi], ah);
            }
            #pragma unroll
            for (int ntp = 0; ntp < 2; ntp++) {
                uint32_t sw = (uint32_t)((((kc << 1) | khalf) ^ bsw[ntp]) << 4);
                ldmx4(Bv[ntp], bb + boff[ntp] + sw);
            }
            #pragma unroll
            for (int mi = 0; mi < 2; mi++)
                #pragma unroll
                for (int ntp = 0; ntp < 2; ntp++)
                    #pragma unroll
                    for (int s = 0; s < 2; s++)
                        mma16816(C[mi][ntp * 2 + s], A[mi],
                                 Bv[ntp][2 * s], Bv[ntp][2 * s + 1]);
        }
    }

    // ---- epilogue: C -> smem [m][o] (stride 66), then coalesced float4 stores ----
    __syncthreads();
    float* sC = (float*)smem;
    const int g   = lane >> 2;
    const int tg2 = (lane & 3) * 2;
    #pragma unroll
    for (int mi = 0; mi < 2; mi++)
        #pragma unroll
        for (int nt = 0; nt < 4; nt++) {
            int mrow = m0 + mi * 16 + g;
            int col  = n0 + nt * 8 + tg2;
            *(float2*)(sC + mrow * 66 + col)       = make_float2(C[mi][nt][0], C[mi][nt][1]);
            *(float2*)(sC + (mrow + 8) * 66 + col) = make_float2(C[mi][nt][2], C[mi][nt][3]);
        }
    __syncthreads();

    #pragma unroll
    for (int it = 0; it < 8; it++) {
        int idx = it * 256 + tid;          // (o, py, q)
        int o   = idx >> 5;
        int rem = idx & 31;
        int py  = rem >> 2;
        int px  = (rem & 3) * 4;
        int mb  = py * 16 + px;
        float4 v;
        v.x = sC[(mb + 0) * 66 + o];
        v.y = sC[(mb + 1) * 66 + o];
        v.z = sC[(mb + 2) * 66 + o];
        v.w = sC[(mb + 3) * 66 + o];
        *(float4*)(out + ((size_t)(b * COUT + o)) * HWSZ + (y0 + py) * WW + (x0 + px)) = v;
    }
}

// ================= launch =================
extern "C" void kernel_launch(void* const* d_in, const int* in_sizes, int n_in,
                              void* d_out, int out_size)
{
    (void)in_sizes; (void)n_in; (void)out_size;
    const float* x    = (const float*)d_in[0];
    const float* w    = (const float*)d_in[1];
    const int*   mask = (const int*)d_in[2];
    float*       out  = (float*)d_out;

    xprep_kernel<<<dim3(HH, BATCH), 256>>>(x);
    wprep_kernel<<<(9 * COUT * CIN + 255) / 256, 256>>>(w);

    cudaFuncSetAttribute(rconv_mma_kernel,
                         cudaFuncAttributeMaxDynamicSharedMemorySize, SMEM_SZ);
    rconv_mma_kernel<<<dim3(98, BATCH), 256, SMEM_SZ>>>(mask, out);
}

// round 9
// speedup vs baseline: 8.9433x; 1.0478x over previous
#include <cuda_runtime.h>
#include <cuda_fp16.h>
#include <cstdint>

#define BATCH 8
#define CIN   64
#define COUT  64
#define HH    112
#define WW    112
#define HWSZ  (HH*WW)

// ---------------- precomputed fp16 planes ----------------
// x_h: [b][y][x][c] (c contiguous: 64*2B = 128B rows)
__device__ __align__(128) __half g_x_h[BATCH * HH * WW * CIN];
// w_h: [t][o][c]
__device__ __align__(128) __half g_w_h[9 * COUT * CIN];

// ================= prep: transpose + fp16 convert =================
__global__ void xprep_kernel(const float* __restrict__ x)
{
    __shared__ float tile[CIN * 113];
    const int y = blockIdx.x, b = blockIdx.y, tid = threadIdx.x;

    for (int i = tid; i < CIN * 28; i += 256) {
        int c = i / 28, q = i - c * 28;
        float4 v = *(const float4*)&x[(((size_t)b * CIN + c) * HH + y) * WW + q * 4];
        float* d = &tile[c * 113 + q * 4];
        d[0] = v.x; d[1] = v.y; d[2] = v.z; d[3] = v.w;
    }
    __syncthreads();

    for (int i = tid; i < 896; i += 256) {
        int xx = i >> 3, cg = i & 7;
        __half h[8];
        #pragma unroll
        for (int k = 0; k < 8; k++)
            h[k] = __float2half(tile[(cg * 8 + k) * 113 + xx]);
        *(uint4*)&g_x_h[((size_t)((b * HH + y) * WW) + xx) * 64 + cg * 8] = *(uint4*)h;
    }
}

__global__ void wprep_kernel(const float* __restrict__ w)
{
    int i = blockIdx.x * 256 + threadIdx.x;
    if (i >= 9 * COUT * CIN) return;
    int c = i & 63, o = (i >> 6) & 63, t = i >> 12;
    g_w_h[(t * COUT + o) * CIN + c] = __float2half(w[o * (CIN * 9) + c * 9 + t]);
}

// ================= base-ISA async/MMA primitives =================
__device__ __forceinline__ uint32_t smem_u32(const void* p) {
    uint32_t a;
    asm("{ .reg .u64 t; cvta.to.shared.u64 t, %1; cvt.u32.u64 %0, t; }" : "=r"(a) : "l"(p));
    return a;
}
__device__ __forceinline__ void cp16(uint32_t dst, const void* src, uint32_t sz) {
    asm volatile("cp.async.cg.shared.global [%0], [%1], 16, %2;"
                 :: "r"(dst), "l"(src), "r"(sz) : "memory");
}
#define CP_COMMIT() asm volatile("cp.async.commit_group;" ::: "memory")
#define CP_WAIT0()  asm volatile("cp.async.wait_group 0;" ::: "memory")

__device__ __forceinline__ void ldmx4(uint32_t* r, uint32_t addr) {
    asm volatile("ldmatrix.sync.aligned.m8n8.x4.shared.b16 {%0,%1,%2,%3}, [%4];"
                 : "=r"(r[0]), "=r"(r[1]), "=r"(r[2]), "=r"(r[3]) : "r"(addr));
}
__device__ __forceinline__ void mma16816(float* c, const uint32_t* a,
                                         uint32_t b0, uint32_t b1) {
    asm volatile("mma.sync.aligned.m16n8k16.row.col.f32.f16.f16.f32 "
                 "{%0,%1,%2,%3}, {%4,%5,%6,%7}, {%8,%9}, {%0,%1,%2,%3};"
                 : "+f"(c[0]), "+f"(c[1]), "+f"(c[2]), "+f"(c[3])
                 : "r"(a[0]), "r"(a[1]), "r"(a[2]), "r"(a[3]), "r"(b0), "r"(b1));
}

// ================= main kernel =================
// 128 threads (4 warps), warp tile 32 (m) x 64 (n) -> 192B LDS per HMMA.
// smem: [0, 23040)   x tile: 180 rows x 128B (XOR-swizzled)
//       [23040, 23168) zero row
//       [23168, 96896) B: ALL 9 taps x 8KB (barrier-free mainloop)
// epilogue reuses [0, 33792) as C[128][66] fp32.
#define X_OFF   0
#define Z_OFF   23040
#define B_OFF   23168
#define B_TAP   8192
#define SMEM_SZ 96896
#define NT      128

__global__ __launch_bounds__(NT, 2)
void rconv_mma_kernel(const int* __restrict__ mask, float* __restrict__ out)
{
    extern __shared__ __align__(128) char smem[];
    const uint32_t sb = smem_u32(smem);

    const int tid  = threadIdx.x;
    const int wid  = tid >> 5;              // 0..3  -> m-tile of 32 positions
    const int lane = tid & 31;
    const int tile = blockIdx.x;            // 0..97
    const int b    = blockIdx.y;
    const int x0   = (tile % 7) * 16;
    const int y0   = (tile / 7) * 8;

    const int m0 = wid * 32;                // warp covers positions m0..m0+31, ALL 64 outputs

    if (tid < 32) ((float*)(smem + Z_OFF))[tid] = 0.0f;

    // ---- per-thread ldmatrix geometry ----
    const int ch      = lane >> 4;          // A k-half
    const int lanerow = lane & 15;
    int  rb[2], mk[2];
    #pragma unroll
    for (int mi = 0; mi < 2; mi++) {
        int p  = m0 + mi * 16 + lanerow;    // position 0..127
        int py = p >> 4, px = p & 15;
        rb[mi] = py * 18 + px;
        mk[mi] = __ldg(&mask[(y0 + py) * WW + (x0 + px)]);
    }
    const int nlocal = (lane & 7) + ((lane >> 4) << 3);
    const int khalf  = (lane >> 3) & 1;
    int boff[4], bsw[4];
    #pragma unroll
    for (int ntp = 0; ntp < 4; ntp++) {     // 4 n16-tiles cover n=64
        int orow = ntp * 16 + nlocal;
        boff[ntp] = orow * 128;
        bsw[ntp]  = orow & 7;
    }
    const uint32_t zaddr = sb + Z_OFF;

    // ---- prologue: stage x tile + ALL 9 B taps, single barrier ----
    for (int i = tid; i < 1440; i += NT) {
        int r  = i >> 3;
        int j  = i & 7;
        int iy = r / 18, ix = r - iy * 18;
        int gy = y0 - 1 + iy, gx = x0 - 1 + ix;
        bool ok = (gy >= 0 && gy < HH && gx >= 0 && gx < WW);
        const __half* src = g_x_h +
            (ok ? (((size_t)((b * HH + gy) * WW + gx)) * CIN + j * 8) : 0);
        uint32_t dst = sb + X_OFF + r * 128 + ((j ^ (r & 7)) << 4);
        cp16(dst, src, ok ? 16u : 0u);
    }
    #pragma unroll
    for (int k = 0; k < 36; k++) {          // 9 taps x 64 o x 8 j = 4608 units
        int i = k * NT + tid;
        int t = i / 512;
        int rem = i & 511;
        int o = rem >> 3, j = rem & 7;
        const __half* src = g_w_h + ((t * COUT + o) * CIN + j * 8);
        uint32_t dst = sb + B_OFF + t * B_TAP + o * 128 + ((j ^ (o & 7)) << 4);
        cp16(dst, src, 16u);
    }
    CP_COMMIT();

    float C[2][8][4];                       // [m16][n8][frag]
    #pragma unroll
    for (int mi = 0; mi < 2; mi++)
        #pragma unroll
        for (int nt = 0; nt < 8; nt++)
            #pragma unroll
            for (int k = 0; k < 4; k++) C[mi][nt][k] = 0.0f;

    CP_WAIT0();
    __syncthreads();

    // ---- barrier-free tap loop (fully unrolled) ----
    #pragma unroll
    for (int t = 0; t < 9; t++) {
        const int kh   = t / 3;
        const int toff = t + kh * 15;        // kh*18 + kw
        int  r128[2], rm[2];
        bool msk[2];
        #pragma unroll
        for (int mi = 0; mi < 2; mi++) {
            int r = rb[mi] + toff;
            r128[mi] = r << 7;
            rm[mi]   = r & 7;
            msk[mi]  = (mk[mi] == t);
        }
        const uint32_t bb = sb + B_OFF + t * B_TAP;

        #pragma unroll
        for (int kc = 0; kc < 4; kc++) {
            uint32_t A[2][4], Bv[4][4];
            #pragma unroll
            for (int mi = 0; mi < 2; mi++) {
                uint32_t sw = (uint32_t)((((kc << 1) | ch) ^ rm[mi]) << 4);
                uint32_t ah = msk[mi] ? zaddr : (sb + X_OFF + r128[mi] + sw);
                ldmx4(A[mi], ah);
            }
            #pragma unroll
            for (int ntp = 0; ntp < 4; ntp++) {
                uint32_t sw = (uint32_t)((((kc << 1) | khalf) ^ bsw[ntp]) << 4);
                ldmx4(Bv[ntp], bb + boff[ntp] + sw);
            }
            #pragma unroll
            for (int mi = 0; mi < 2; mi++)
                #pragma unroll
                for (int ntp = 0; ntp < 4; ntp++)
                    #pragma unroll
                    for (int s = 0; s < 2; s++)
                        mma16816(C[mi][ntp * 2 + s], A[mi],
                                 Bv[ntp][2 * s], Bv[ntp][2 * s + 1]);
        }
    }

    // ---- epilogue: C -> smem [m][o] (stride 66), then coalesced float4 stores ----
    __syncthreads();
    float* sC = (float*)smem;
    const int g   = lane >> 2;
    const int tg2 = (lane & 3) * 2;
    #pragma unroll
    for (int mi = 0; mi < 2; mi++)
        #pragma unroll
        for (int nt = 0; nt < 8; nt++) {
            int mrow = m0 + mi * 16 + g;
            int col  = nt * 8 + tg2;
            *(float2*)(sC + mrow * 66 + col)       = make_float2(C[mi][nt][0], C[mi][nt][1]);
            *(float2*)(sC + (mrow + 8) * 66 + col) = make_float2(C[mi][nt][2], C[mi][nt][3]);
        }
    __syncthreads();

    #pragma unroll
    for (int it = 0; it < 16; it++) {
        int idx = it * NT + tid;           // (o, py, q)
        int o   = idx >> 5;
        int rem = idx & 31;
        int py  = rem >> 2;
        int px  = (rem & 3) * 4;
        int mb  = py * 16 + px;
        float4 v;
        v.x = sC[(mb + 0) * 66 + o];
        v.y = sC[(mb + 1) * 66 + o];
        v.z = sC[(mb + 2) * 66 + o];
        v.w = sC[(mb + 3) * 66 + o];
        *(float4*)(out + ((size_t)(b * COUT + o)) * HWSZ + (y0 + py) * WW + (x0 + px)) = v;
    }
}

// ================= launch =================
extern "C" void kernel_launch(void* const* d_in, const int* in_sizes, int n_in,
                              void* d_out, int out_size)
{
    (void)in_sizes; (void)n_in; (void)out_size;
    const float* x    = (const float*)d_in[0];
    const float* w    = (const float*)d_in[1];
    const int*   mask = (const int*)d_in[2];
    float*       out  = (float*)d_out;

    xprep_kernel<<<dim3(HH, BATCH), 256>>>(x);
    wprep_kernel<<<(9 * COUT * CIN + 255) / 256, 256>>>(w);

    cudaFuncSetAttribute(rconv_mma_kernel,
                         cudaFuncAttributeMaxDynamicSharedMemorySize, SMEM_SZ);
    rconv_mma_kernel<<<dim3(98, BATCH), NT, SMEM_SZ>>>(mask, out);
}